// round 1
// baseline (speedup 1.0000x reference)
#include <cuda_runtime.h>
#include <cuda_bf16.h>
#include <mma.h>

using namespace nvcuda;

#define NN 16384        // max nodes
#define NH 64           // hidden
#define INF 256         // in feats

// ---- scratch (device globals; no allocation allowed) ----
__device__ int   g_outdeg[NN];
__device__ int   g_indeg[NN];
__device__ float g_h[NN * NH];
__device__ float g_agg[NN * NH];
__device__ __nv_bfloat16 g_hi[NN * NH];
__device__ __nv_bfloat16 g_lo[NN * NH];

// ---------------------------------------------------------------- zero
__global__ void zero_kernel(int n) {
    int t = blockIdx.x * blockDim.x + threadIdx.x;
    if (t < n * NH) g_agg[t] = 0.0f;
    if (t < n) { g_outdeg[t] = 0; g_indeg[t] = 0; }
}

// ---------------------------------------------------------------- degrees
__global__ void deg_kernel(const int* __restrict__ src,
                           const int* __restrict__ dst, int E) {
    int e = blockIdx.x * blockDim.x + threadIdx.x;
    if (e >= E) return;
    atomicAdd(&g_outdeg[src[e]], 1);
    atomicAdd(&g_indeg[dst[e]], 1);
}

// ---------------------------------------------------------------- projection
// h[row] = rsqrt(max(outdeg,1)) * (features[row] @ W)
// 8 rows per block, 64 threads (one per hidden unit); W column read from L1.
__global__ void proj_kernel(const float* __restrict__ feats,
                            const float* __restrict__ W) {
    __shared__ float sf[8][INF];
    int r0 = blockIdx.x * 8;
    int tid = threadIdx.x;  // 0..63
    for (int i = tid; i < 8 * INF; i += 64) {
        int rr = i >> 8, k = i & (INF - 1);
        sf[rr][k] = feats[(size_t)(r0 + rr) * INF + k];
    }
    __syncthreads();
    float sc[8];
#pragma unroll
    for (int rr = 0; rr < 8; rr++)
        sc[rr] = rsqrtf((float)max(g_outdeg[r0 + rr], 1));
    int j = tid;
    float acc[8];
#pragma unroll
    for (int rr = 0; rr < 8; rr++) acc[rr] = 0.0f;
#pragma unroll 4
    for (int k = 0; k < INF; k++) {
        float w = __ldg(&W[k * NH + j]);
#pragma unroll
        for (int rr = 0; rr < 8; rr++) acc[rr] = fmaf(sf[rr][k], w, acc[rr]);
    }
#pragma unroll
    for (int rr = 0; rr < 8; rr++)
        g_h[(size_t)(r0 + rr) * NH + j] = acc[rr] * sc[rr];
}

// ---------------------------------------------------------------- edge scatter
// 16 threads per edge, each does a float4 chunk + 4 atomicAdds into agg[dst].
__global__ void edge_kernel(const int* __restrict__ src,
                            const int* __restrict__ dst,
                            const int* __restrict__ node_id,
                            const float* __restrict__ alpha,
                            const int* __restrict__ gene_num_p,
                            int E) {
    long long t = (long long)blockIdx.x * blockDim.x + threadIdx.x;
    int e = (int)(t >> 4);
    int c = (int)(t & 15);
    if (e >= E) return;
    int gn = gene_num_p ? __ldg(gene_num_p) : 2000;
    int s = src[e], d = dst[e];
    int sid = node_id[s], did = node_id[d];
    int idx = gn + 1;
    if (sid >= 0 && did >= 0)      idx = gn;
    else if (sid >= 0 && did < 0)  idx = sid;
    else if (did >= 0 && sid < 0)  idx = did;
    float a = __ldg(&alpha[idx]);
    float4 v = ((const float4*)g_h)[(size_t)s * 16 + c];
    float* ap = g_agg + (size_t)d * NH + c * 4;
    atomicAdd(ap + 0, v.x * a);
    atomicAdd(ap + 1, v.y * a);
    atomicAdd(ap + 2, v.z * a);
    atomicAdd(ap + 3, v.w * a);
}

// ---------------------------------------------------------------- rst + split
__global__ void rst_kernel(const float* __restrict__ bias,
                           float* __restrict__ out_rst, int n) {
    int t = blockIdx.x * blockDim.x + threadIdx.x;
    if (t >= n * NH) return;
    int node = t >> 6, j = t & 63;
    float v = g_agg[t] * rsqrtf((float)max(g_indeg[node], 1)) + bias[j];
    out_rst[t] = v;
    __nv_bfloat16 h = __float2bfloat16(v);
    g_hi[t] = h;
    g_lo[t] = __float2bfloat16(v - __bfloat162float(h));
}

// ---------------------------------------------------------------- adj = R R^T
// bf16 split-pair GEMM: C = hi*hi^T + hi*lo^T + lo*hi^T, fp32 accumulate.
// CTA tile 128x128, K=64. 8 warps in 4x2 grid; warp tile 32x64 (2x4 wmma frags).
#define LDS_ 72   // padded row stride (144 B, multiple of 16 B)

__global__ __launch_bounds__(256, 2)
void gemm_kernel(float* __restrict__ C, int n) {
    extern __shared__ __nv_bfloat16 smem[];
    __nv_bfloat16* sAhi = smem;
    __nv_bfloat16* sAlo = smem + 128 * LDS_;
    __nv_bfloat16* sBhi = smem + 2 * 128 * LDS_;
    __nv_bfloat16* sBlo = smem + 3 * 128 * LDS_;

    int tid = threadIdx.x;
    size_t baseA = (size_t)blockIdx.y * 128 * NH;  // elements into g_hi/g_lo
    size_t baseB = (size_t)blockIdx.x * 128 * NH;

    // load 4 tiles of 128x64 bf16 as uint4 (8 per row)
    for (int i = tid; i < 1024; i += 256) {
        int r = i >> 3, c = i & 7;
        uint4 ahi = ((const uint4*)(g_hi + baseA + (size_t)r * NH))[c];
        uint4 alo = ((const uint4*)(g_lo + baseA + (size_t)r * NH))[c];
        uint4 bhi = ((const uint4*)(g_hi + baseB + (size_t)r * NH))[c];
        uint4 blo = ((const uint4*)(g_lo + baseB + (size_t)r * NH))[c];
        *(uint4*)(sAhi + r * LDS_ + c * 8) = ahi;
        *(uint4*)(sAlo + r * LDS_ + c * 8) = alo;
        *(uint4*)(sBhi + r * LDS_ + c * 8) = bhi;
        *(uint4*)(sBlo + r * LDS_ + c * 8) = blo;
    }
    __syncthreads();

    int w  = tid >> 5;
    int wm = w >> 1;   // 0..3  -> 32-row band
    int wn = w & 1;    // 0..1  -> 64-col band

    wmma::fragment<wmma::accumulator, 16, 16, 16, float> acc[2][4];
#pragma unroll
    for (int mi = 0; mi < 2; mi++)
#pragma unroll
        for (int ni = 0; ni < 4; ni++)
            wmma::fill_fragment(acc[mi][ni], 0.0f);

    const __nv_bfloat16* Ap[3] = {sAhi, sAhi, sAlo};
    const __nv_bfloat16* Bp[3] = {sBhi, sBlo, sBhi};

#pragma unroll
    for (int p = 0; p < 3; p++) {
        const __nv_bfloat16* A = Ap[p] + (wm * 32) * LDS_;
        const __nv_bfloat16* B = Bp[p] + (wn * 64) * LDS_;
#pragma unroll
        for (int k = 0; k < NH; k += 16) {
            wmma::fragment<wmma::matrix_a, 16, 16, 16, __nv_bfloat16, wmma::row_major> af[2];
            wmma::fragment<wmma::matrix_b, 16, 16, 16, __nv_bfloat16, wmma::col_major> bf[4];
#pragma unroll
            for (int mi = 0; mi < 2; mi++)
                wmma::load_matrix_sync(af[mi], A + mi * 16 * LDS_ + k, LDS_);
#pragma unroll
            for (int ni = 0; ni < 4; ni++)
                wmma::load_matrix_sync(bf[ni], B + ni * 16 * LDS_ + k, LDS_);
#pragma unroll
            for (int mi = 0; mi < 2; mi++)
#pragma unroll
                for (int ni = 0; ni < 4; ni++)
                    wmma::mma_sync(acc[mi][ni], af[mi], bf[ni], acc[mi][ni]);
        }
    }

#pragma unroll
    for (int mi = 0; mi < 2; mi++)
#pragma unroll
        for (int ni = 0; ni < 4; ni++) {
            size_t row = (size_t)blockIdx.y * 128 + wm * 32 + mi * 16;
            size_t col = (size_t)blockIdx.x * 128 + wn * 64 + ni * 16;
            wmma::store_matrix_sync(C + row * n + col, acc[mi][ni], n,
                                    wmma::mem_row_major);
        }
}

// ---------------------------------------------------------------- launch
extern "C" void kernel_launch(void* const* d_in, const int* in_sizes, int n_in,
                              void* d_out, int out_size) {
    const float* features = (const float*)d_in[0];
    const float* W        = (const float*)d_in[1];
    const float* bias     = (const float*)d_in[2];
    const float* alpha    = (const float*)d_in[3];
    const int*   src      = (const int*)d_in[4];
    const int*   dst      = (const int*)d_in[5];
    const int*   node_id  = (const int*)d_in[6];
    const int*   gene_p   = (n_in > 7) ? (const int*)d_in[7] : nullptr;

    int n = in_sizes[0] / INF;   // 16384
    int E = in_sizes[4];         // 524288

    float* out_adj = (float*)d_out;
    float* out_rst = out_adj + (size_t)n * n;

    zero_kernel<<<(n * NH + 255) / 256, 256>>>(n);
    deg_kernel<<<(E + 255) / 256, 256>>>(src, dst, E);
    proj_kernel<<<n / 8, 64>>>(features, W);
    {
        long long tot = (long long)E * 16;
        int blocks = (int)((tot + 255) / 256);
        edge_kernel<<<blocks, 256>>>(src, dst, node_id, alpha, gene_p, E);
    }
    rst_kernel<<<(n * NH + 255) / 256, 256>>>(bias, out_rst, n);

    cudaFuncSetAttribute(gemm_kernel,
                         cudaFuncAttributeMaxDynamicSharedMemorySize,
                         4 * 128 * LDS_ * (int)sizeof(__nv_bfloat16));
    dim3 grid(n / 128, n / 128);
    gemm_kernel<<<grid, 256, 4 * 128 * LDS_ * (int)sizeof(__nv_bfloat16)>>>(out_adj, n);
}

// round 2
// speedup vs baseline: 1.7192x; 1.7192x over previous
#include <cuda_runtime.h>
#include <cuda_fp16.h>
#include <mma.h>

using namespace nvcuda;

#define NN 16384        // nodes
#define NH 64           // hidden
#define INF 256         // in feats
#define EMAX 524288     // edges

// ---- scratch (device globals; no allocation allowed) ----
__device__ int   g_outdeg[NN];
__device__ int   g_indeg[NN];
__device__ int   g_rowstart[NN + 1];
__device__ int   g_cursor[NN];
__device__ int   g_esrc[EMAX];
__device__ float g_ealpha[EMAX];
__device__ float g_h[NN * NH];
__device__ __half g_u[NN * NH];   // fp16 hi
__device__ __half g_v[NN * NH];   // fp16 round(2x - hi) = hi + 2*lo

// ---------------------------------------------------------------- zero degs
__global__ void zero_kernel(int n) {
    int t = blockIdx.x * blockDim.x + threadIdx.x;
    if (t < n) { g_outdeg[t] = 0; g_indeg[t] = 0; }
}

// ---------------------------------------------------------------- degrees
__global__ void deg_kernel(const int* __restrict__ src,
                           const int* __restrict__ dst, int E) {
    int e = blockIdx.x * blockDim.x + threadIdx.x;
    if (e >= E) return;
    atomicAdd(&g_outdeg[src[e]], 1);
    atomicAdd(&g_indeg[dst[e]], 1);
}

// ---------------------------------------------------------------- prefix scan
// Single CTA, 1024 threads, 16 values each: exclusive scan of indeg -> rowstart.
__global__ void scan_kernel(int n, int E) {
    __shared__ int warpsum[32];
    int tid = threadIdx.x;
    const int PER = 16;              // 1024*16 = 16384
    int base = tid * PER;
    int local[PER];
    int s = 0;
#pragma unroll
    for (int i = 0; i < PER; i++) {
        local[i] = s;
        int idx = base + i;
        s += (idx < n) ? g_indeg[idx] : 0;
    }
    int lane = tid & 31, wid = tid >> 5;
    // inclusive warp scan of s
    int pref = s;
#pragma unroll
    for (int d = 1; d < 32; d <<= 1) {
        int t = __shfl_up_sync(0xFFFFFFFFu, pref, d);
        if (lane >= d) pref += t;
    }
    if (lane == 31) warpsum[wid] = pref;
    __syncthreads();
    if (wid == 0) {
        int v = warpsum[lane];
#pragma unroll
        for (int d = 1; d < 32; d <<= 1) {
            int t = __shfl_up_sync(0xFFFFFFFFu, v, d);
            if (lane >= d) v += t;
        }
        warpsum[lane] = v;   // inclusive warp totals
    }
    __syncthreads();
    int warpoff = (wid == 0) ? 0 : warpsum[wid - 1];
    int off = warpoff + (pref - s);   // exclusive offset of this thread
#pragma unroll
    for (int i = 0; i < PER; i++) {
        int idx = base + i;
        if (idx < n) {
            int o = off + local[i];
            g_rowstart[idx] = o;
            g_cursor[idx]   = o;
        }
    }
    if (tid == 0) g_rowstart[n] = E;
}

// ---------------------------------------------------------------- projection
// h[row] = rsqrt(max(outdeg,1)) * (features[row] @ W)
__global__ void proj_kernel(const float* __restrict__ feats,
                            const float* __restrict__ W) {
    __shared__ float sf[8][INF];
    int r0 = blockIdx.x * 8;
    int tid = threadIdx.x;  // 0..63
    for (int i = tid; i < 8 * INF; i += 64) {
        int rr = i >> 8, k = i & (INF - 1);
        sf[rr][k] = feats[(size_t)(r0 + rr) * INF + k];
    }
    __syncthreads();
    float sc[8];
#pragma unroll
    for (int rr = 0; rr < 8; rr++)
        sc[rr] = rsqrtf((float)max(g_outdeg[r0 + rr], 1));
    int j = tid;
    float acc[8];
#pragma unroll
    for (int rr = 0; rr < 8; rr++) acc[rr] = 0.0f;
#pragma unroll 4
    for (int k = 0; k < INF; k++) {
        float w = __ldg(&W[k * NH + j]);
#pragma unroll
        for (int rr = 0; rr < 8; rr++) acc[rr] = fmaf(sf[rr][k], w, acc[rr]);
    }
#pragma unroll
    for (int rr = 0; rr < 8; rr++)
        g_h[(size_t)(r0 + rr) * NH + j] = acc[rr] * sc[rr];
}

// ---------------------------------------------------------------- edge bucket
// Compute per-edge alpha and bucket (src, alpha) by dst into CSR slots.
__global__ void scatter_kernel(const int* __restrict__ src,
                               const int* __restrict__ dst,
                               const int* __restrict__ node_id,
                               const float* __restrict__ alpha,
                               const int* __restrict__ gene_num_p,
                               int E) {
    int e = blockIdx.x * blockDim.x + threadIdx.x;
    if (e >= E) return;
    int gn = gene_num_p ? __ldg(gene_num_p) : 2000;
    int s = src[e], d = dst[e];
    int sid = node_id[s], did = node_id[d];
    int idx = gn + 1;
    if (sid >= 0 && did >= 0)      idx = gn;
    else if (sid >= 0 && did < 0)  idx = sid;
    else if (did >= 0 && sid < 0)  idx = did;
    float a = __ldg(&alpha[idx]);
    int pos = atomicAdd(&g_cursor[d], 1);
    g_esrc[pos]   = s;
    g_ealpha[pos] = a;
}

// ---------------------------------------------------------------- gather + rst
// Warp per node: agg over incoming edges in regs, then in-degree norm + bias,
// write rst (fp32) and the fp16 split pair (u, v).
__global__ void gather_kernel(const float* __restrict__ bias,
                              float* __restrict__ out_rst, int n) {
    int warp = (blockIdx.x * blockDim.x + threadIdx.x) >> 5;
    int lane = threadIdx.x & 31;
    if (warp >= n) return;
    int start = g_rowstart[warp];
    int end   = g_rowstart[warp + 1];
    const float2* H = (const float2*)g_h;
    float2 acc = make_float2(0.0f, 0.0f);
    for (int k = start; k < end; k++) {
        int s  = g_esrc[k];
        float a = g_ealpha[k];
        float2 hv = H[(size_t)s * 32 + lane];
        acc.x = fmaf(hv.x, a, acc.x);
        acc.y = fmaf(hv.y, a, acc.y);
    }
    float sc = rsqrtf((float)max(end - start, 1));
    float b0 = bias[lane * 2], b1 = bias[lane * 2 + 1];
    float v0 = acc.x * sc + b0;
    float v1 = acc.y * sc + b1;
    size_t o = (size_t)warp * NH + lane * 2;
    out_rst[o]     = v0;
    out_rst[o + 1] = v1;
    __half u0 = __float2half_rn(v0);
    __half u1 = __float2half_rn(v1);
    __half w0 = __float2half_rn(2.0f * v0 - __half2float(u0));  // hi + 2*lo
    __half w1 = __float2half_rn(2.0f * v1 - __half2float(u1));
    ((__half2*)g_u)[(size_t)warp * 32 + lane] = __halves2half2(u0, u1);
    ((__half2*)g_v)[(size_t)warp * 32 + lane] = __halves2half2(w0, w1);
}

// ---------------------------------------------------------------- adj = R R^T
// fp16 split-pair symmetric GEMM:
//   tile(i,j) = 0.5 * ( u_i v_j^T + v_i u_j^T )   (== hi hi^T + hi lo^T + lo hi^T + O(2^-12))
// Only j>=i computed; mirror tile written via smem-staged transpose.
// CTA tile 128x128, K=64; 8 warps 4x2; warp tile 32x64.
#define LDS_ 72   // half row stride (mult of 8)
#define TLD_ 132  // float staging row stride (mult of 4)

__global__ __launch_bounds__(256, 2)
void gemm_kernel(float* __restrict__ C, int n) {
    int bx = blockIdx.x, by = blockIdx.y;
    if (bx < by) return;   // symmetric: compute upper-tri tiles only
    extern __shared__ __half smem[];
    __half* sUi = smem;
    __half* sVi = smem + 128 * LDS_;
    __half* sUj;
    __half* sVj;

    int tid = threadIdx.x;
    size_t baseI = (size_t)by * 128 * NH;
    size_t baseJ = (size_t)bx * 128 * NH;

    bool diag = (bx == by);
    if (diag) { sUj = sUi; sVj = sVi; }
    else      { sUj = smem + 2 * 128 * LDS_; sVj = smem + 3 * 128 * LDS_; }

    // load tiles (128x64 halves each) as uint4 (16B = 8 halves, 8 per row)
    for (int i = tid; i < 1024; i += 256) {
        int r = i >> 3, c = i & 7;
        uint4 ui = ((const uint4*)(g_u + baseI + (size_t)r * NH))[c];
        uint4 vi = ((const uint4*)(g_v + baseI + (size_t)r * NH))[c];
        *(uint4*)(sUi + r * LDS_ + c * 8) = ui;
        *(uint4*)(sVi + r * LDS_ + c * 8) = vi;
        if (!diag) {
            uint4 uj = ((const uint4*)(g_u + baseJ + (size_t)r * NH))[c];
            uint4 vj = ((const uint4*)(g_v + baseJ + (size_t)r * NH))[c];
            *(uint4*)(sUj + r * LDS_ + c * 8) = uj;
            *(uint4*)(sVj + r * LDS_ + c * 8) = vj;
        }
    }
    __syncthreads();

    int w  = tid >> 5;
    int wm = w >> 1;   // 0..3  -> 32-row band
    int wn = w & 1;    // 0..1  -> 64-col band

    wmma::fragment<wmma::accumulator, 16, 16, 16, float> acc[2][4];
#pragma unroll
    for (int mi = 0; mi < 2; mi++)
#pragma unroll
        for (int ni = 0; ni < 4; ni++)
            wmma::fill_fragment(acc[mi][ni], 0.0f);

    const __half* Ap[2] = { sUi, sVi };
    const __half* Bp[2] = { sVj, sUj };

#pragma unroll
    for (int p = 0; p < 2; p++) {
        const __half* A = Ap[p] + (wm * 32) * LDS_;
        const __half* B = Bp[p] + (wn * 64) * LDS_;
#pragma unroll
        for (int k = 0; k < NH; k += 16) {
            wmma::fragment<wmma::matrix_a, 16, 16, 16, __half, wmma::row_major> af[2];
            wmma::fragment<wmma::matrix_b, 16, 16, 16, __half, wmma::col_major> bf[4];
#pragma unroll
            for (int mi = 0; mi < 2; mi++)
                wmma::load_matrix_sync(af[mi], A + mi * 16 * LDS_ + k, LDS_);
#pragma unroll
            for (int ni = 0; ni < 4; ni++)
                wmma::load_matrix_sync(bf[ni], B + ni * 16 * LDS_ + k, LDS_);
#pragma unroll
            for (int mi = 0; mi < 2; mi++)
#pragma unroll
                for (int ni = 0; ni < 4; ni++)
                    wmma::mma_sync(acc[mi][ni], af[mi], bf[ni], acc[mi][ni]);
        }
    }

    // scale by 0.5 (symmetrization)
#pragma unroll
    for (int mi = 0; mi < 2; mi++)
#pragma unroll
        for (int ni = 0; ni < 4; ni++)
#pragma unroll
            for (int t = 0; t < acc[mi][ni].num_elements; t++)
                acc[mi][ni].x[t] *= 0.5f;

    // own tile store (coalesced)
#pragma unroll
    for (int mi = 0; mi < 2; mi++)
#pragma unroll
        for (int ni = 0; ni < 4; ni++) {
            size_t row = (size_t)by * 128 + wm * 32 + mi * 16;
            size_t col = (size_t)bx * 128 + wn * 64 + ni * 16;
            wmma::store_matrix_sync(C + row * n + col, acc[mi][ni], n,
                                    wmma::mem_row_major);
        }

    if (diag) return;

    // mirror tile: stage to smem (row-major, ld TLD_), then transposed write
    __syncthreads();                       // done reading input tiles
    float* st = (float*)smem;              // 128 x TLD_ floats (67.6KB <= 73.7KB)
#pragma unroll
    for (int mi = 0; mi < 2; mi++)
#pragma unroll
        for (int ni = 0; ni < 4; ni++)
            wmma::store_matrix_sync(st + (wm * 32 + mi * 16) * TLD_ + wn * 64 + ni * 16,
                                    acc[mi][ni], TLD_, wmma::mem_row_major);
    __syncthreads();
    size_t j0 = (size_t)bx * 128, i0 = (size_t)by * 128;
    for (int idx = tid; idx < 128 * 128; idx += 256) {
        int r = idx >> 7;        // row within mirror tile (j-dir)
        int c = idx & 127;       // col within mirror tile (i-dir)
        C[(j0 + r) * n + i0 + c] = st[c * TLD_ + r];
    }
}

// ---------------------------------------------------------------- launch
extern "C" void kernel_launch(void* const* d_in, const int* in_sizes, int n_in,
                              void* d_out, int out_size) {
    const float* features = (const float*)d_in[0];
    const float* W        = (const float*)d_in[1];
    const float* bias     = (const float*)d_in[2];
    const float* alpha    = (const float*)d_in[3];
    const int*   src      = (const int*)d_in[4];
    const int*   dst      = (const int*)d_in[5];
    const int*   node_id  = (const int*)d_in[6];
    const int*   gene_p   = (n_in > 7) ? (const int*)d_in[7] : nullptr;

    int n = in_sizes[0] / INF;   // 16384
    int E = in_sizes[4];         // 524288

    float* out_adj = (float*)d_out;
    float* out_rst = out_adj + (size_t)n * n;

    zero_kernel<<<(n + 255) / 256, 256>>>(n);
    deg_kernel<<<(E + 255) / 256, 256>>>(src, dst, E);
    scan_kernel<<<1, 1024>>>(n, E);
    proj_kernel<<<n / 8, 64>>>(features, W);
    scatter_kernel<<<(E + 255) / 256, 256>>>(src, dst, node_id, alpha, gene_p, E);
    gather_kernel<<<(n * 32 + 255) / 256, 256>>>(bias, out_rst, n);

    int smem_bytes = 4 * 128 * LDS_ * (int)sizeof(__half);   // 73728
    cudaFuncSetAttribute(gemm_kernel,
                         cudaFuncAttributeMaxDynamicSharedMemorySize, smem_bytes);
    dim3 grid(n / 128, n / 128);
    gemm_kernel<<<grid, 256, smem_bytes>>>(out_adj, n);
}

// round 4
// speedup vs baseline: 1.8188x; 1.0579x over previous
#include <cuda_runtime.h>
#include <cuda_fp16.h>
#include <mma.h>

using namespace nvcuda;

#define NN 16384        // nodes
#define NH 64           // hidden
#define INF 256         // in feats
#define EMAX 524288     // edges

// ---- scratch (device globals; no allocation allowed) ----
__device__ int   g_outdeg[NN];
__device__ int   g_indeg[NN];
__device__ int   g_rowstart[NN + 1];
__device__ int   g_cursor[NN];
__device__ int   g_esrc[EMAX];
__device__ float g_ealpha[EMAX];
__device__ float g_h[NN * NH];
__device__ __half g_u[NN * NH];   // 0.5 * fp16(x)            (pre-scaled hi)
__device__ __half g_v[NN * NH];   // fp16(2x - fp16(x)) = hi + 2*lo

// ---------------------------------------------------------------- zero degs
__global__ void zero_kernel(int n) {
    int t = blockIdx.x * blockDim.x + threadIdx.x;
    if (t < n) { g_outdeg[t] = 0; g_indeg[t] = 0; }
}

// ---------------------------------------------------------------- degrees
__global__ void deg_kernel(const int* __restrict__ src,
                           const int* __restrict__ dst, int E) {
    int e = blockIdx.x * blockDim.x + threadIdx.x;
    if (e >= E) return;
    atomicAdd(&g_outdeg[src[e]], 1);
    atomicAdd(&g_indeg[dst[e]], 1);
}

// ---------------------------------------------------------------- prefix scan
// Single CTA, 1024 threads, 16 values each: exclusive scan of indeg -> rowstart.
__global__ void scan_kernel(int n, int E) {
    __shared__ int warpsum[32];
    int tid = threadIdx.x;
    const int PER = 16;              // 1024*16 = 16384
    int base = tid * PER;
    int local[PER];
    int s = 0;
#pragma unroll
    for (int i = 0; i < PER; i++) {
        local[i] = s;
        int idx = base + i;
        s += (idx < n) ? g_indeg[idx] : 0;
    }
    int lane = tid & 31, wid = tid >> 5;
    int pref = s;
#pragma unroll
    for (int d = 1; d < 32; d <<= 1) {
        int t = __shfl_up_sync(0xFFFFFFFFu, pref, d);
        if (lane >= d) pref += t;
    }
    if (lane == 31) warpsum[wid] = pref;
    __syncthreads();
    if (wid == 0) {
        int v = warpsum[lane];
#pragma unroll
        for (int d = 1; d < 32; d <<= 1) {
            int t = __shfl_up_sync(0xFFFFFFFFu, v, d);
            if (lane >= d) v += t;
        }
        warpsum[lane] = v;
    }
    __syncthreads();
    int warpoff = (wid == 0) ? 0 : warpsum[wid - 1];
    int off = warpoff + (pref - s);
#pragma unroll
    for (int i = 0; i < PER; i++) {
        int idx = base + i;
        if (idx < n) {
            int o = off + local[i];
            g_rowstart[idx] = o;
            g_cursor[idx]   = o;
        }
    }
    if (tid == 0) g_rowstart[n] = E;
}

// ---------------------------------------------------------------- projection
// 32 rows/CTA, 256 threads (4 groups x 64 cols); k unrolled x4, float4 smem.
__global__ __launch_bounds__(256) void proj_kernel(const float* __restrict__ feats,
                                                   const float* __restrict__ W) {
    __shared__ float sf[32][INF];
    int r0 = blockIdx.x * 32;
    int tid = threadIdx.x;
    const float4* F4 = (const float4*)(feats + (size_t)r0 * INF);
    float4* S4 = (float4*)&sf[0][0];
    for (int i = tid; i < 32 * INF / 4; i += 256) S4[i] = F4[i];
    __syncthreads();
    int g = tid >> 6;         // 0..3
    int j = tid & 63;         // output column
    int rbase = g * 8;
    float acc[8];
#pragma unroll
    for (int rr = 0; rr < 8; rr++) acc[rr] = 0.0f;
    for (int k = 0; k < INF; k += 4) {
        float w0 = __ldg(&W[(k + 0) * NH + j]);
        float w1 = __ldg(&W[(k + 1) * NH + j]);
        float w2 = __ldg(&W[(k + 2) * NH + j]);
        float w3 = __ldg(&W[(k + 3) * NH + j]);
#pragma unroll
        for (int rr = 0; rr < 8; rr++) {
            float4 f = *(const float4*)&sf[rbase + rr][k];
            acc[rr] = fmaf(f.x, w0, acc[rr]);
            acc[rr] = fmaf(f.y, w1, acc[rr]);
            acc[rr] = fmaf(f.z, w2, acc[rr]);
            acc[rr] = fmaf(f.w, w3, acc[rr]);
        }
    }
#pragma unroll
    for (int rr = 0; rr < 8; rr++) {
        int row = r0 + rbase + rr;
        float sc = rsqrtf((float)max(g_outdeg[row], 1));
        g_h[(size_t)row * NH + j] = acc[rr] * sc;
    }
}

// ---------------------------------------------------------------- edge bucket
__global__ void scatter_kernel(const int* __restrict__ src,
                               const int* __restrict__ dst,
                               const int* __restrict__ node_id,
                               const float* __restrict__ alpha,
                               const int* __restrict__ gene_num_p,
                               int E) {
    int e = blockIdx.x * blockDim.x + threadIdx.x;
    if (e >= E) return;
    int gn = gene_num_p ? __ldg(gene_num_p) : 2000;
    int s = src[e], d = dst[e];
    int sid = node_id[s], did = node_id[d];
    int idx = gn + 1;
    if (sid >= 0 && did >= 0)      idx = gn;
    else if (sid >= 0 && did < 0)  idx = sid;
    else if (did >= 0 && sid < 0)  idx = did;
    float a = __ldg(&alpha[idx]);
    int pos = atomicAdd(&g_cursor[d], 1);
    g_esrc[pos]   = s;
    g_ealpha[pos] = a;
}

// ---------------------------------------------------------------- gather + rst
__global__ void gather_kernel(const float* __restrict__ bias,
                              float* __restrict__ out_rst, int n) {
    int warp = (blockIdx.x * blockDim.x + threadIdx.x) >> 5;
    int lane = threadIdx.x & 31;
    if (warp >= n) return;
    int start = g_rowstart[warp];
    int end   = g_rowstart[warp + 1];
    const float2* H = (const float2*)g_h;
    float2 acc = make_float2(0.0f, 0.0f);
    for (int k = start; k < end; k++) {
        int s  = g_esrc[k];
        float a = g_ealpha[k];
        float2 hv = H[(size_t)s * 32 + lane];
        acc.x = fmaf(hv.x, a, acc.x);
        acc.y = fmaf(hv.y, a, acc.y);
    }
    float sc = rsqrtf((float)max(end - start, 1));
    float b0 = bias[lane * 2], b1 = bias[lane * 2 + 1];
    float v0 = acc.x * sc + b0;
    float v1 = acc.y * sc + b1;
    size_t o = (size_t)warp * NH + lane * 2;
    out_rst[o]     = v0;
    out_rst[o + 1] = v1;
    __half u0 = __float2half_rn(v0);
    __half u1 = __float2half_rn(v1);
    __half w0 = __float2half_rn(2.0f * v0 - __half2float(u0));  // hi + 2*lo
    __half w1 = __float2half_rn(2.0f * v1 - __half2float(u1));
    // pre-scale u by 0.5 (exact in fp16): folds the symmetrization scale
    __half up0 = __float2half_rn(0.5f * __half2float(u0));
    __half up1 = __float2half_rn(0.5f * __half2float(u1));
    ((__half2*)g_u)[(size_t)warp * 32 + lane] = __halves2half2(up0, up1);
    ((__half2*)g_v)[(size_t)warp * 32 + lane] = __halves2half2(w0, w1);
}

// ---------------------------------------------------------------- adj = R R^T
// tile(i,j) = u'_i v_j^T + v_i u'_j^T  (u' = 0.5*hi)  == hi hi^T + hi lo^T + lo hi^T
// Triangular grid (bx >= by); mirror tile via col-major smem staging + STG.128.
#define LDS_ 72   // half row stride (mult of 8)
#define TLD_ 132  // float staging col stride (mult of 4)

__global__ __launch_bounds__(256, 2)
void gemm_kernel(float* __restrict__ C, int n) {
    // decode linear triangular index -> (bx, by), by <= bx
    int t = blockIdx.x;
    int bx = (int)((sqrtf(8.0f * (float)t + 1.0f) - 1.0f) * 0.5f);
    while ((bx + 1) * (bx + 2) / 2 <= t) bx++;
    while (bx * (bx + 1) / 2 > t) bx--;
    int by = t - bx * (bx + 1) / 2;

    extern __shared__ __half smem[];
    __half* sUi = smem;
    __half* sVi = smem + 128 * LDS_;
    __half* sUj;
    __half* sVj;

    int tid = threadIdx.x;
    size_t baseI = (size_t)by * 128 * NH;
    size_t baseJ = (size_t)bx * 128 * NH;

    bool diag = (bx == by);
    if (diag) { sUj = sUi; sVj = sVi; }
    else      { sUj = smem + 2 * 128 * LDS_; sVj = smem + 3 * 128 * LDS_; }

    for (int i = tid; i < 1024; i += 256) {
        int r = i >> 3, c = i & 7;
        uint4 ui = ((const uint4*)(g_u + baseI + (size_t)r * NH))[c];
        uint4 vi = ((const uint4*)(g_v + baseI + (size_t)r * NH))[c];
        *(uint4*)(sUi + r * LDS_ + c * 8) = ui;
        *(uint4*)(sVi + r * LDS_ + c * 8) = vi;
        if (!diag) {
            uint4 uj = ((const uint4*)(g_u + baseJ + (size_t)r * NH))[c];
            uint4 vj = ((const uint4*)(g_v + baseJ + (size_t)r * NH))[c];
            *(uint4*)(sUj + r * LDS_ + c * 8) = uj;
            *(uint4*)(sVj + r * LDS_ + c * 8) = vj;
        }
    }
    __syncthreads();

    int w  = tid >> 5;
    int wm = w >> 1;   // 0..3  -> 32-row band
    int wn = w & 1;    // 0..1  -> 64-col band

    wmma::fragment<wmma::accumulator, 16, 16, 16, float> acc[2][4];
#pragma unroll
    for (int mi = 0; mi < 2; mi++)
#pragma unroll
        for (int ni = 0; ni < 4; ni++)
            wmma::fill_fragment(acc[mi][ni], 0.0f);

    const __half* Ap[2] = { sUi, sVi };
    const __half* Bp[2] = { sVj, sUj };

#pragma unroll
    for (int p = 0; p < 2; p++) {
        const __half* A = Ap[p] + (wm * 32) * LDS_;
        const __half* B = Bp[p] + (wn * 64) * LDS_;
#pragma unroll
        for (int k = 0; k < NH; k += 16) {
            wmma::fragment<wmma::matrix_a, 16, 16, 16, __half, wmma::row_major> af[2];
            wmma::fragment<wmma::matrix_b, 16, 16, 16, __half, wmma::col_major> bf[4];
#pragma unroll
            for (int mi = 0; mi < 2; mi++)
                wmma::load_matrix_sync(af[mi], A + mi * 16 * LDS_ + k, LDS_);
#pragma unroll
            for (int ni = 0; ni < 4; ni++)
                wmma::load_matrix_sync(bf[ni], B + ni * 16 * LDS_ + k, LDS_);
#pragma unroll
            for (int mi = 0; mi < 2; mi++)
#pragma unroll
                for (int ni = 0; ni < 4; ni++)
                    wmma::mma_sync(acc[mi][ni], af[mi], bf[ni], acc[mi][ni]);
        }
    }

    // own tile store (coalesced)
#pragma unroll
    for (int mi = 0; mi < 2; mi++)
#pragma unroll
        for (int ni = 0; ni < 4; ni++) {
            size_t row = (size_t)by * 128 + wm * 32 + mi * 16;
            size_t col = (size_t)bx * 128 + wn * 64 + ni * 16;
            wmma::store_matrix_sync(C + row * n + col, acc[mi][ni], n,
                                    wmma::mem_row_major);
        }

    if (diag) return;

    // mirror tile: stage col-major -> st[c*TLD_ + r]; then contiguous float4 writes
    __syncthreads();                       // done reading input tiles
    float* st = (float*)smem;              // 128 cols x TLD_ (67.6KB <= 73.7KB)
#pragma unroll
    for (int mi = 0; mi < 2; mi++)
#pragma unroll
        for (int ni = 0; ni < 4; ni++)
            wmma::store_matrix_sync(st + (size_t)(wn * 64 + ni * 16) * TLD_
                                       + (wm * 32 + mi * 16),
                                    acc[mi][ni], TLD_, wmma::mem_col_major);
    __syncthreads();
    size_t j0 = (size_t)bx * 128, i0 = (size_t)by * 128;
    for (int idx = tid; idx < 128 * 32; idx += 256) {
        int c  = idx >> 5;          // mirror-tile row (column index of own tile)
        int r4 = idx & 31;          // float4 chunk along own-tile rows
        float4 v = *(const float4*)(st + (size_t)c * TLD_ + r4 * 4);
        *(float4*)(C + (j0 + c) * n + i0 + r4 * 4) = v;
    }
}

// ---------------------------------------------------------------- launch
extern "C" void kernel_launch(void* const* d_in, const int* in_sizes, int n_in,
                              void* d_out, int out_size) {
    const float* features = (const float*)d_in[0];
    const float* W        = (const float*)d_in[1];
    const float* bias     = (const float*)d_in[2];
    const float* alpha    = (const float*)d_in[3];
    const int*   src      = (const int*)d_in[4];
    const int*   dst      = (const int*)d_in[5];
    const int*   node_id  = (const int*)d_in[6];
    const int*   gene_p   = (n_in > 7) ? (const int*)d_in[7] : nullptr;

    int n = in_sizes[0] / INF;   // 16384
    int E = in_sizes[4];         // 524288

    float* out_adj = (float*)d_out;
    float* out_rst = out_adj + (size_t)n * n;

    zero_kernel<<<(n + 255) / 256, 256>>>(n);
    deg_kernel<<<(E + 255) / 256, 256>>>(src, dst, E);
    scan_kernel<<<1, 1024>>>(n, E);
    proj_kernel<<<n / 32, 256>>>(features, W);
    scatter_kernel<<<(E + 255) / 256, 256>>>(src, dst, node_id, alpha, gene_p, E);
    gather_kernel<<<(n * 32 + 255) / 256, 256>>>(bias, out_rst, n);

    int smem_bytes = 4 * 128 * LDS_ * (int)sizeof(__half);   // 73728
    cudaFuncSetAttribute(gemm_kernel,
                         cudaFuncAttributeMaxDynamicSharedMemorySize, smem_bytes);
    int ntile = n / 128;
    int tri = ntile * (ntile + 1) / 2;   // 8256
    gemm_kernel<<<tri, 256, smem_bytes>>>(out_adj, n);
}

// round 6
// speedup vs baseline: 1.9008x; 1.0451x over previous
#include <cuda_runtime.h>
#include <cuda_fp16.h>
#include <mma.h>

using namespace nvcuda;

#define NN 16384        // nodes
#define NH 64           // hidden
#define INF 256         // in feats
#define EMAX 524288     // edges

// ---- scratch (device globals; no allocation allowed) ----
__device__ int   g_outdeg[NN];
__device__ int   g_indeg[NN];
__device__ int   g_rowstart[NN + 1];
__device__ int   g_cursor[NN];
__device__ int   g_esrc[EMAX];
__device__ float g_ealpha[EMAX];
__device__ float g_h[NN * NH];
__device__ __half g_u[NN * NH];   // 0.5 * fp16(x)            (pre-scaled hi)
__device__ __half g_v[NN * NH];   // fp16(2x - fp16(x)) = hi + 2*lo

// ---------------------------------------------------------------- zero degs
__global__ void zero_kernel(int n) {
    int t = blockIdx.x * blockDim.x + threadIdx.x;
    if (t < n) { g_outdeg[t] = 0; g_indeg[t] = 0; }
}

// ---------------------------------------------------------------- degrees
__global__ void deg_kernel(const int* __restrict__ src,
                           const int* __restrict__ dst, int E) {
    int e = blockIdx.x * blockDim.x + threadIdx.x;
    if (e >= E) return;
    atomicAdd(&g_outdeg[src[e]], 1);
    atomicAdd(&g_indeg[dst[e]], 1);
}

// ---------------------------------------------------------------- prefix scan
// Single CTA, 1024 threads, 16 values each: exclusive scan of indeg -> rowstart.
__global__ void scan_kernel(int n, int E) {
    __shared__ int warpsum[32];
    int tid = threadIdx.x;
    const int PER = 16;              // 1024*16 = 16384
    int base = tid * PER;
    int local[PER];
    int s = 0;
#pragma unroll
    for (int i = 0; i < PER; i++) {
        local[i] = s;
        int idx = base + i;
        s += (idx < n) ? g_indeg[idx] : 0;
    }
    int lane = tid & 31, wid = tid >> 5;
    int pref = s;
#pragma unroll
    for (int d = 1; d < 32; d <<= 1) {
        int t = __shfl_up_sync(0xFFFFFFFFu, pref, d);
        if (lane >= d) pref += t;
    }
    if (lane == 31) warpsum[wid] = pref;
    __syncthreads();
    if (wid == 0) {
        int v = warpsum[lane];
#pragma unroll
        for (int d = 1; d < 32; d <<= 1) {
            int t = __shfl_up_sync(0xFFFFFFFFu, v, d);
            if (lane >= d) v += t;
        }
        warpsum[lane] = v;
    }
    __syncthreads();
    int warpoff = (wid == 0) ? 0 : warpsum[wid - 1];
    int off = warpoff + (pref - s);
#pragma unroll
    for (int i = 0; i < PER; i++) {
        int idx = base + i;
        if (idx < n) {
            int o = off + local[i];
            g_rowstart[idx] = o;
            g_cursor[idx]   = o;
        }
    }
    if (tid == 0) g_rowstart[n] = E;
}

// ---------------------------------------------------------------- projection
// 16 rows/CTA -> 1024 CTAs (grid-limited occupancy fix). 4 col-groups x 4 rows.
__global__ __launch_bounds__(256) void proj_kernel(const float* __restrict__ feats,
                                                   const float* __restrict__ W) {
    __shared__ float sf[16][INF];
    int r0 = blockIdx.x * 16;
    int tid = threadIdx.x;
    const float4* F4 = (const float4*)(feats + (size_t)r0 * INF);
    float4* S4 = (float4*)&sf[0][0];
    for (int i = tid; i < 16 * INF / 4; i += 256) S4[i] = F4[i];
    __syncthreads();
    int g = tid >> 6;         // 0..3
    int j = tid & 63;         // output column
    int rbase = g * 4;
    float acc[4] = {0.f, 0.f, 0.f, 0.f};
    for (int k = 0; k < INF; k += 4) {
        float w0 = __ldg(&W[(k + 0) * NH + j]);
        float w1 = __ldg(&W[(k + 1) * NH + j]);
        float w2 = __ldg(&W[(k + 2) * NH + j]);
        float w3 = __ldg(&W[(k + 3) * NH + j]);
#pragma unroll
        for (int rr = 0; rr < 4; rr++) {
            float4 f = *(const float4*)&sf[rbase + rr][k];
            acc[rr] = fmaf(f.x, w0, acc[rr]);
            acc[rr] = fmaf(f.y, w1, acc[rr]);
            acc[rr] = fmaf(f.z, w2, acc[rr]);
            acc[rr] = fmaf(f.w, w3, acc[rr]);
        }
    }
#pragma unroll
    for (int rr = 0; rr < 4; rr++) {
        int row = r0 + rbase + rr;
        float sc = rsqrtf((float)max(g_outdeg[row], 1));
        g_h[(size_t)row * NH + j] = acc[rr] * sc;
    }
}

// ---------------------------------------------------------------- edge bucket
__global__ void scatter_kernel(const int* __restrict__ src,
                               const int* __restrict__ dst,
                               const int* __restrict__ node_id,
                               const float* __restrict__ alpha,
                               const int* __restrict__ gene_num_p,
                               int E) {
    int e = blockIdx.x * blockDim.x + threadIdx.x;
    if (e >= E) return;
    int gn = gene_num_p ? __ldg(gene_num_p) : 2000;
    int s = src[e], d = dst[e];
    int sid = node_id[s], did = node_id[d];
    int idx = gn + 1;
    if (sid >= 0 && did >= 0)      idx = gn;
    else if (sid >= 0 && did < 0)  idx = sid;
    else if (did >= 0 && sid < 0)  idx = did;
    float a = __ldg(&alpha[idx]);
    int pos = atomicAdd(&g_cursor[d], 1);
    g_esrc[pos]   = s;
    g_ealpha[pos] = a;
}

// ---------------------------------------------------------------- gather + rst
__global__ void gather_kernel(const float* __restrict__ bias,
                              float* __restrict__ out_rst, int n) {
    int warp = (blockIdx.x * blockDim.x + threadIdx.x) >> 5;
    int lane = threadIdx.x & 31;
    if (warp >= n) return;
    int start = g_rowstart[warp];
    int end   = g_rowstart[warp + 1];
    const float2* H = (const float2*)g_h;
    float2 acc = make_float2(0.0f, 0.0f);
    for (int k = start; k < end; k++) {
        int s  = g_esrc[k];
        float a = g_ealpha[k];
        float2 hv = H[(size_t)s * 32 + lane];
        acc.x = fmaf(hv.x, a, acc.x);
        acc.y = fmaf(hv.y, a, acc.y);
    }
    float sc = rsqrtf((float)max(end - start, 1));
    float b0 = bias[lane * 2], b1 = bias[lane * 2 + 1];
    float v0 = acc.x * sc + b0;
    float v1 = acc.y * sc + b1;
    size_t o = (size_t)warp * NH + lane * 2;
    out_rst[o]     = v0;
    out_rst[o + 1] = v1;
    __half u0 = __float2half_rn(v0);
    __half u1 = __float2half_rn(v1);
    __half w0 = __float2half_rn(2.0f * v0 - __half2float(u0));  // hi + 2*lo
    __half w1 = __float2half_rn(2.0f * v1 - __half2float(u1));
    // pre-scale u by 0.5 (exact in fp16): folds the symmetrization scale
    __half up0 = __float2half_rn(0.5f * __half2float(u0));
    __half up1 = __float2half_rn(0.5f * __half2float(u1));
    ((__half2*)g_u)[(size_t)warp * 32 + lane] = __halves2half2(up0, up1);
    ((__half2*)g_v)[(size_t)warp * 32 + lane] = __halves2half2(w0, w1);
}

// ---------------------------------------------------------------- adj = R R^T
// tile(i,j) = u'_i v_j^T + v_i u'_j^T  (u' = 0.5*hi)  == hi hi^T + hi lo^T + lo hi^T
// Triangular grid (bx >= by).
// Own tile: direct row-major wmma store. Mirror tile: direct COL-MAJOR wmma
// store at base C + col0*n + row0 (writes C[(col0+c)*n + row0+r] = acc(r,c)),
// i.e. the transposed tile straight from registers — no smem staging, no syncs.
#define LDS_ 72   // half row stride (mult of 8)

__global__ __launch_bounds__(256, 2)
void gemm_kernel(float* __restrict__ C, int n) {
    // decode linear triangular index -> (bx, by), by <= bx
    int t = blockIdx.x;
    int bx = (int)((sqrtf(8.0f * (float)t + 1.0f) - 1.0f) * 0.5f);
    while ((bx + 1) * (bx + 2) / 2 <= t) bx++;
    while (bx * (bx + 1) / 2 > t) bx--;
    int by = t - bx * (bx + 1) / 2;

    extern __shared__ __half smem[];
    __half* sUi = smem;
    __half* sVi = smem + 128 * LDS_;
    __half* sUj;
    __half* sVj;

    int tid = threadIdx.x;
    size_t baseI = (size_t)by * 128 * NH;
    size_t baseJ = (size_t)bx * 128 * NH;

    bool diag = (bx == by);
    if (diag) { sUj = sUi; sVj = sVi; }
    else      { sUj = smem + 2 * 128 * LDS_; sVj = smem + 3 * 128 * LDS_; }

    for (int i = tid; i < 1024; i += 256) {
        int r = i >> 3, c = i & 7;
        uint4 ui = ((const uint4*)(g_u + baseI + (size_t)r * NH))[c];
        uint4 vi = ((const uint4*)(g_v + baseI + (size_t)r * NH))[c];
        *(uint4*)(sUi + r * LDS_ + c * 8) = ui;
        *(uint4*)(sVi + r * LDS_ + c * 8) = vi;
        if (!diag) {
            uint4 uj = ((const uint4*)(g_u + baseJ + (size_t)r * NH))[c];
            uint4 vj = ((const uint4*)(g_v + baseJ + (size_t)r * NH))[c];
            *(uint4*)(sUj + r * LDS_ + c * 8) = uj;
            *(uint4*)(sVj + r * LDS_ + c * 8) = vj;
        }
    }
    __syncthreads();

    int w  = tid >> 5;
    int wm = w >> 1;   // 0..3  -> 32-row band
    int wn = w & 1;    // 0..1  -> 64-col band

    wmma::fragment<wmma::accumulator, 16, 16, 16, float> acc[2][4];
#pragma unroll
    for (int mi = 0; mi < 2; mi++)
#pragma unroll
        for (int ni = 0; ni < 4; ni++)
            wmma::fill_fragment(acc[mi][ni], 0.0f);

    const __half* Ap[2] = { sUi, sVi };
    const __half* Bp[2] = { sVj, sUj };

#pragma unroll
    for (int p = 0; p < 2; p++) {
        const __half* A = Ap[p] + (wm * 32) * LDS_;
        const __half* B = Bp[p] + (wn * 64) * LDS_;
#pragma unroll
        for (int k = 0; k < NH; k += 16) {
            wmma::fragment<wmma::matrix_a, 16, 16, 16, __half, wmma::row_major> af[2];
            wmma::fragment<wmma::matrix_b, 16, 16, 16, __half, wmma::col_major> bf[4];
#pragma unroll
            for (int mi = 0; mi < 2; mi++)
                wmma::load_matrix_sync(af[mi], A + mi * 16 * LDS_ + k, LDS_);
#pragma unroll
            for (int ni = 0; ni < 4; ni++)
                wmma::load_matrix_sync(bf[ni], B + ni * 16 * LDS_ + k, LDS_);
#pragma unroll
            for (int mi = 0; mi < 2; mi++)
#pragma unroll
                for (int ni = 0; ni < 4; ni++)
                    wmma::mma_sync(acc[mi][ni], af[mi], bf[ni], acc[mi][ni]);
        }
    }

    // own tile store (row-major, coalesced)
#pragma unroll
    for (int mi = 0; mi < 2; mi++)
#pragma unroll
        for (int ni = 0; ni < 4; ni++) {
            size_t row = (size_t)by * 128 + wm * 32 + mi * 16;
            size_t col = (size_t)bx * 128 + wn * 64 + ni * 16;
            wmma::store_matrix_sync(C + row * n + col, acc[mi][ni], n,
                                    wmma::mem_row_major);
        }

    // mirror tile store (col-major == transposed write), direct from registers
    if (!diag) {
#pragma unroll
        for (int mi = 0; mi < 2; mi++)
#pragma unroll
            for (int ni = 0; ni < 4; ni++) {
                size_t row = (size_t)by * 128 + wm * 32 + mi * 16;
                size_t col = (size_t)bx * 128 + wn * 64 + ni * 16;
                wmma::store_matrix_sync(C + col * n + row, acc[mi][ni], n,
                                        wmma::mem_col_major);
            }
    }
}

// ---------------------------------------------------------------- launch
extern "C" void kernel_launch(void* const* d_in, const int* in_sizes, int n_in,
                              void* d_out, int out_size) {
    const float* features = (const float*)d_in[0];
    const float* W        = (const float*)d_in[1];
    const float* bias     = (const float*)d_in[2];
    const float* alpha    = (const float*)d_in[3];
    const int*   src      = (const int*)d_in[4];
    const int*   dst      = (const int*)d_in[5];
    const int*   node_id  = (const int*)d_in[6];
    const int*   gene_p   = (n_in > 7) ? (const int*)d_in[7] : nullptr;

    int n = in_sizes[0] / INF;   // 16384
    int E = in_sizes[4];         // 524288

    float* out_adj = (float*)d_out;
    float* out_rst = out_adj + (size_t)n * n;

    zero_kernel<<<(n + 255) / 256, 256>>>(n);
    deg_kernel<<<(E + 255) / 256, 256>>>(src, dst, E);
    scan_kernel<<<1, 1024>>>(n, E);
    proj_kernel<<<n / 16, 256>>>(features, W);
    scatter_kernel<<<(E + 255) / 256, 256>>>(src, dst, node_id, alpha, gene_p, E);
    gather_kernel<<<(n * 32 + 255) / 256, 256>>>(bias, out_rst, n);

    int smem_bytes = 4 * 128 * LDS_ * (int)sizeof(__half);   // 73728
    cudaFuncSetAttribute(gemm_kernel,
                         cudaFuncAttributeMaxDynamicSharedMemorySize, smem_bytes);
    int ntile = n / 128;
    int tri = ntile * (ntile + 1) / 2;   // 8256
    gemm_kernel<<<tri, 256, smem_bytes>>>(out_adj, n);
}

// round 9
// speedup vs baseline: 1.9235x; 1.0119x over previous
#include <cuda_runtime.h>
#include <cuda_fp16.h>
#include <mma.h>

using namespace nvcuda;

#define NN 16384        // nodes
#define NH 64           // hidden
#define INF 256         // in feats
#define EMAX 524288     // edges

// ---- scratch (device globals; no allocation allowed) ----
__device__ int    g_outdeg[NN];
__device__ int    g_indeg[NN];
__device__ int    g_rowstart[NN + 1];
__device__ int    g_cursor[NN];
__device__ int    g_esrc[EMAX];
__device__ float  g_ealpha[EMAX];
__device__ float  g_h[NN * NH];
__device__ __half g_fhi[NN * INF];    // hi of (s * features)
__device__ __half g_flo[NN * INF];    // lo of (s * features)
__device__ __half g_Whi[INF * NH];
__device__ __half g_Wlo[INF * NH];
__device__ __half g_u[NN * NH];       // 0.5 * fp16(x)   (pre-scaled hi)
__device__ __half g_v[NN * NH];       // fp16(2x - fp16(x)) = hi + 2*lo

// ---------------------------------------------------------------- zero degs
__global__ void zero_kernel(int n) {
    int t = blockIdx.x * blockDim.x + threadIdx.x;
    if (t < n) { g_outdeg[t] = 0; g_indeg[t] = 0; }
}

// ---------------------------------------------------------------- degrees
__global__ void deg_kernel(const int* __restrict__ src,
                           const int* __restrict__ dst, int E) {
    int e = blockIdx.x * blockDim.x + threadIdx.x;
    if (e >= E) return;
    atomicAdd(&g_outdeg[src[e]], 1);
    atomicAdd(&g_indeg[dst[e]], 1);
}

// ---------------------------------------------------------------- feat conv
// scaled = rsqrt(max(outdeg,1)) * f;  split into fp16 hi/lo pair.
__global__ void conv_feat_kernel(const float* __restrict__ feats, int n) {
    int t = blockIdx.x * blockDim.x + threadIdx.x;     // over n*INF/2
    if (t >= n * INF / 2) return;
    int row = t / (INF / 2);
    float sc = rsqrtf((float)max(g_outdeg[row], 1));
    float2 f = ((const float2*)feats)[t];
    float a = f.x * sc, b = f.y * sc;
    __half ha = __float2half_rn(a), hb = __float2half_rn(b);
    __half la = __float2half_rn(a - __half2float(ha));
    __half lb = __float2half_rn(b - __half2float(hb));
    ((__half2*)g_fhi)[t] = __halves2half2(ha, hb);
    ((__half2*)g_flo)[t] = __halves2half2(la, lb);
}

// ---------------------------------------------------------------- W conv
__global__ void conv_W_kernel(const float* __restrict__ W) {
    int t = blockIdx.x * blockDim.x + threadIdx.x;
    if (t >= INF * NH) return;
    float w = W[t];
    __half h = __float2half_rn(w);
    g_Whi[t] = h;
    g_Wlo[t] = __float2half_rn(w - __half2float(h));
}

// ---------------------------------------------------------------- prefix scan
__global__ void scan_kernel(int n, int E) {
    __shared__ int warpsum[32];
    int tid = threadIdx.x;
    const int PER = 16;              // 1024*16 = 16384
    int base = tid * PER;
    int local[PER];
    int s = 0;
#pragma unroll
    for (int i = 0; i < PER; i++) {
        local[i] = s;
        int idx = base + i;
        s += (idx < n) ? g_indeg[idx] : 0;
    }
    int lane = tid & 31, wid = tid >> 5;
    int pref = s;
#pragma unroll
    for (int d = 1; d < 32; d <<= 1) {
        int t = __shfl_up_sync(0xFFFFFFFFu, pref, d);
        if (lane >= d) pref += t;
    }
    if (lane == 31) warpsum[wid] = pref;
    __syncthreads();
    if (wid == 0) {
        int v = warpsum[lane];
#pragma unroll
        for (int d = 1; d < 32; d <<= 1) {
            int t = __shfl_up_sync(0xFFFFFFFFu, v, d);
            if (lane >= d) v += t;
        }
        warpsum[lane] = v;
    }
    __syncthreads();
    int warpoff = (wid == 0) ? 0 : warpsum[wid - 1];
    int off = warpoff + (pref - s);
#pragma unroll
    for (int i = 0; i < PER; i++) {
        int idx = base + i;
        if (idx < n) {
            int o = off + local[i];
            g_rowstart[idx] = o;
            g_cursor[idx]   = o;
        }
    }
    if (tid == 0) g_rowstart[n] = E;
}

// ---------------------------------------------------------------- projection (wmma)
// h = (s*F) @ W with 3-term split: fhi*Whi + flo*Whi + fhi*Wlo (fp32 acc).
// CTA: 64 rows, 4 warps (warp = 16 rows x 64 cols). Full W in smem; A chunked.
#define PLD 72   // smem row stride (halves)

__global__ __launch_bounds__(128) void proj_kernel() {
    extern __shared__ __half ps[];
    __half* sWhi = ps;                       // 256 x PLD
    __half* sWlo = ps + INF * PLD;           // 256 x PLD
    __half* sAhi = ps + 2 * INF * PLD;       // 64 x PLD
    __half* sAlo = ps + 2 * INF * PLD + 64 * PLD;

    int tid = threadIdx.x;
    int r0 = blockIdx.x * 64;

    // load W (hi, lo): 256 rows x 64 halves (8 uint4 per row)
    for (int i = tid; i < INF * 8; i += 128) {
        int r = i >> 3, c = i & 7;
        *(uint4*)(sWhi + r * PLD + c * 8) = ((const uint4*)(g_Whi + r * NH))[c];
        *(uint4*)(sWlo + r * PLD + c * 8) = ((const uint4*)(g_Wlo + r * NH))[c];
    }

    int w = tid >> 5;
    wmma::fragment<wmma::accumulator, 16, 16, 16, float> acc[4];
#pragma unroll
    for (int ni = 0; ni < 4; ni++) wmma::fill_fragment(acc[ni], 0.0f);

    for (int kc = 0; kc < 4; kc++) {
        // stage A chunk: 64 rows x 64 halves from columns kc*64
        __syncthreads();
        for (int i = tid; i < 64 * 8; i += 128) {
            int r = i >> 3, c = i & 7;
            *(uint4*)(sAhi + r * PLD + c * 8) =
                ((const uint4*)(g_fhi + (size_t)(r0 + r) * INF + kc * 64))[c];
            *(uint4*)(sAlo + r * PLD + c * 8) =
                ((const uint4*)(g_flo + (size_t)(r0 + r) * INF + kc * 64))[c];
        }
        __syncthreads();
#pragma unroll
        for (int kk = 0; kk < 4; kk++) {
            wmma::fragment<wmma::matrix_a, 16, 16, 16, __half, wmma::row_major> ah, al;
            wmma::load_matrix_sync(ah, sAhi + (w * 16) * PLD + kk * 16, PLD);
            wmma::load_matrix_sync(al, sAlo + (w * 16) * PLD + kk * 16, PLD);
            int wr = kc * 64 + kk * 16;
#pragma unroll
            for (int ni = 0; ni < 4; ni++) {
                wmma::fragment<wmma::matrix_b, 16, 16, 16, __half, wmma::row_major> bh, bl;
                wmma::load_matrix_sync(bh, sWhi + (size_t)wr * PLD + ni * 16, PLD);
                wmma::load_matrix_sync(bl, sWlo + (size_t)wr * PLD + ni * 16, PLD);
                wmma::mma_sync(acc[ni], ah, bh, acc[ni]);
                wmma::mma_sync(acc[ni], al, bh, acc[ni]);
                wmma::mma_sync(acc[ni], ah, bl, acc[ni]);
            }
        }
    }
#pragma unroll
    for (int ni = 0; ni < 4; ni++)
        wmma::store_matrix_sync(g_h + (size_t)(r0 + w * 16) * NH + ni * 16,
                                acc[ni], NH, wmma::mem_row_major);
}

// ---------------------------------------------------------------- edge bucket
__global__ void scatter_kernel(const int* __restrict__ src,
                               const int* __restrict__ dst,
                               const int* __restrict__ node_id,
                               const float* __restrict__ alpha,
                               const int* __restrict__ gene_num_p,
                               int E) {
    int e = blockIdx.x * blockDim.x + threadIdx.x;
    if (e >= E) return;
    int gn = gene_num_p ? __ldg(gene_num_p) : 2000;
    int s = src[e], d = dst[e];
    int sid = node_id[s], did = node_id[d];
    int idx = gn + 1;
    if (sid >= 0 && did >= 0)      idx = gn;
    else if (sid >= 0 && did < 0)  idx = sid;
    else if (did >= 0 && sid < 0)  idx = did;
    float a = __ldg(&alpha[idx]);
    int pos = atomicAdd(&g_cursor[d], 1);
    g_esrc[pos]   = s;
    g_ealpha[pos] = a;
}

// ---------------------------------------------------------------- gather + rst
__global__ void gather_kernel(const float* __restrict__ bias,
                              float* __restrict__ out_rst, int n) {
    int warp = (blockIdx.x * blockDim.x + threadIdx.x) >> 5;
    int lane = threadIdx.x & 31;
    if (warp >= n) return;
    int start = g_rowstart[warp];
    int end   = g_rowstart[warp + 1];
    const float2* H = (const float2*)g_h;
    float2 acc = make_float2(0.0f, 0.0f);
    for (int k = start; k < end; k++) {
        int s  = g_esrc[k];
        float a = g_ealpha[k];
        float2 hv = H[(size_t)s * 32 + lane];
        acc.x = fmaf(hv.x, a, acc.x);
        acc.y = fmaf(hv.y, a, acc.y);
    }
    float sc = rsqrtf((float)max(end - start, 1));
    float b0 = bias[lane * 2], b1 = bias[lane * 2 + 1];
    float v0 = acc.x * sc + b0;
    float v1 = acc.y * sc + b1;
    size_t o = (size_t)warp * NH + lane * 2;
    out_rst[o]     = v0;
    out_rst[o + 1] = v1;
    __half u0 = __float2half_rn(v0);
    __half u1 = __float2half_rn(v1);
    __half w0 = __float2half_rn(2.0f * v0 - __half2float(u0));  // hi + 2*lo
    __half w1 = __float2half_rn(2.0f * v1 - __half2float(u1));
    __half up0 = __float2half_rn(0.5f * __half2float(u0));
    __half up1 = __float2half_rn(0.5f * __half2float(u1));
    ((__half2*)g_u)[(size_t)warp * 32 + lane] = __halves2half2(up0, up1);
    ((__half2*)g_v)[(size_t)warp * 32 + lane] = __halves2half2(w0, w1);
}

// ---------------------------------------------------------------- adj = R R^T
// tile(i,j) = u'_i v_j^T + v_i u'_j^T  (u' = 0.5*hi). Triangular grid (bx>=by).
// 512 threads / 16 warps (warp tile 32x32) -> 32 warps/SM at 2 CTAs/SM for
// MMA/store overlap. Mirror tile stored col-major direct from registers.
#define LDS_ 72   // half row stride (mult of 8)

__global__ __launch_bounds__(512, 2)
void gemm_kernel(float* __restrict__ C, int n) {
    // decode linear triangular index -> (bx, by), by <= bx
    int t = blockIdx.x;
    int bx = (int)((sqrtf(8.0f * (float)t + 1.0f) - 1.0f) * 0.5f);
    while ((bx + 1) * (bx + 2) / 2 <= t) bx++;
    while (bx * (bx + 1) / 2 > t) bx--;
    int by = t - bx * (bx + 1) / 2;

    extern __shared__ __half smem[];
    __half* sUi = smem;
    __half* sVi = smem + 128 * LDS_;
    __half* sUj;
    __half* sVj;

    int tid = threadIdx.x;
    size_t baseI = (size_t)by * 128 * NH;
    size_t baseJ = (size_t)bx * 128 * NH;

    bool diag = (bx == by);
    if (diag) { sUj = sUi; sVj = sVi; }
    else      { sUj = smem + 2 * 128 * LDS_; sVj = smem + 3 * 128 * LDS_; }

    for (int i = tid; i < 1024; i += 512) {
        int r = i >> 3, c = i & 7;
        uint4 ui = ((const uint4*)(g_u + baseI + (size_t)r * NH))[c];
        uint4 vi = ((const uint4*)(g_v + baseI + (size_t)r * NH))[c];
        *(uint4*)(sUi + r * LDS_ + c * 8) = ui;
        *(uint4*)(sVi + r * LDS_ + c * 8) = vi;
        if (!diag) {
            uint4 uj = ((const uint4*)(g_u + baseJ + (size_t)r * NH))[c];
            uint4 vj = ((const uint4*)(g_v + baseJ + (size_t)r * NH))[c];
            *(uint4*)(sUj + r * LDS_ + c * 8) = uj;
            *(uint4*)(sVj + r * LDS_ + c * 8) = vj;
        }
    }
    __syncthreads();

    int w  = tid >> 5;
    int wm = w >> 2;   // 0..3 -> 32-row band
    int wn = w & 3;    // 0..3 -> 32-col band

    wmma::fragment<wmma::accumulator, 16, 16, 16, float> acc[2][2];
#pragma unroll
    for (int mi = 0; mi < 2; mi++)
#pragma unroll
        for (int ni = 0; ni < 2; ni++)
            wmma::fill_fragment(acc[mi][ni], 0.0f);

    const __half* Ap[2] = { sUi, sVi };
    const __half* Bp[2] = { sVj, sUj };

#pragma unroll
    for (int p = 0; p < 2; p++) {
        const __half* A = Ap[p] + (wm * 32) * LDS_;
        const __half* B = Bp[p] + (wn * 32) * LDS_;
#pragma unroll
        for (int k = 0; k < NH; k += 16) {
            wmma::fragment<wmma::matrix_a, 16, 16, 16, __half, wmma::row_major> af[2];
#pragma unroll
            for (int mi = 0; mi < 2; mi++)
                wmma::load_matrix_sync(af[mi], A + mi * 16 * LDS_ + k, LDS_);
#pragma unroll
            for (int ni = 0; ni < 2; ni++) {
                wmma::fragment<wmma::matrix_b, 16, 16, 16, __half, wmma::col_major> bf;
                wmma::load_matrix_sync(bf, B + ni * 16 * LDS_ + k, LDS_);
#pragma unroll
                for (int mi = 0; mi < 2; mi++)
                    wmma::mma_sync(acc[mi][ni], af[mi], bf, acc[mi][ni]);
            }
        }
    }

    // own tile store (row-major, coalesced)
#pragma unroll
    for (int mi = 0; mi < 2; mi++)
#pragma unroll
        for (int ni = 0; ni < 2; ni++) {
            size_t row = (size_t)by * 128 + wm * 32 + mi * 16;
            size_t col = (size_t)bx * 128 + wn * 32 + ni * 16;
            wmma::store_matrix_sync(C + row * n + col, acc[mi][ni], n,
                                    wmma::mem_row_major);
        }

    // mirror tile store (col-major == transposed write), direct from registers
    if (!diag) {
#pragma unroll
        for (int mi = 0; mi < 2; mi++)
#pragma unroll
            for (int ni = 0; ni < 2; ni++) {
                size_t row = (size_t)by * 128 + wm * 32 + mi * 16;
                size_t col = (size_t)bx * 128 + wn * 32 + ni * 16;
                wmma::store_matrix_sync(C + col * n + row, acc[mi][ni], n,
                                        wmma::mem_col_major);
            }
    }
}

// ---------------------------------------------------------------- launch
extern "C" void kernel_launch(void* const* d_in, const int* in_sizes, int n_in,
                              void* d_out, int out_size) {
    const float* features = (const float*)d_in[0];
    const float* W        = (const float*)d_in[1];
    const float* bias     = (const float*)d_in[2];
    const float* alpha    = (const float*)d_in[3];
    const int*   src      = (const int*)d_in[4];
    const int*   dst      = (const int*)d_in[5];
    const int*   node_id  = (const int*)d_in[6];
    const int*   gene_p   = (n_in > 7) ? (const int*)d_in[7] : nullptr;

    int n = in_sizes[0] / INF;   // 16384
    int E = in_sizes[4];         // 524288

    float* out_adj = (float*)d_out;
    float* out_rst = out_adj + (size_t)n * n;

    zero_kernel<<<(n + 255) / 256, 256>>>(n);
    deg_kernel<<<(E + 255) / 256, 256>>>(src, dst, E);
    conv_feat_kernel<<<(n * INF / 2 + 255) / 256, 256>>>(features, n);
    conv_W_kernel<<<(INF * NH + 255) / 256, 256>>>(W);
    scan_kernel<<<1, 1024>>>(n, E);

    int psmem = (2 * INF + 2 * 64) * PLD * (int)sizeof(__half);  // 92160
    cudaFuncSetAttribute(proj_kernel,
                         cudaFuncAttributeMaxDynamicSharedMemorySize, psmem);
    proj_kernel<<<n / 64, 128, psmem>>>();

    scatter_kernel<<<(E + 255) / 256, 256>>>(src, dst, node_id, alpha, gene_p, E);
    gather_kernel<<<(n * 32 + 255) / 256, 256>>>(bias, out_rst, n);

    int smem_bytes = 4 * 128 * LDS_ * (int)sizeof(__half);   // 73728
    cudaFuncSetAttribute(gemm_kernel,
                         cudaFuncAttributeMaxDynamicSharedMemorySize, smem_bytes);
    int ntile = n / 128;
    int tri = ntile * (ntile + 1) / 2;   // 8256
    gemm_kernel<<<tri, 512, smem_bytes>>>(out_adj, n);
}